// round 14
// baseline (speedup 1.0000x reference)
#include <cuda_runtime.h>
#include <cuda_bf16.h>
#include <cstdint>

#define BATCH 4
#define SEQ   2048
#define DIN   128
#define HDIM  64
#define ROWS  (BATCH*SEQ)        // 8192
#define TQ    32                 // q rows per block
#define KT2   64                 // k cols per tile
#define NKB2  (SEQ/KT2)          // 32

// ---- device scratch ----
__device__ float g_q [ROWS*HDIM];
__device__ float g_k [ROWS*HDIM];
__device__ __nv_bfloat16 g_vth[BATCH*HDIM*SEQ];   // V^T hi, [b][h][s]
__device__ __nv_bfloat16 g_vtl[BATCH*HDIM*SEQ];   // V^T lo
__device__ float g_q2[ROWS];
__device__ float g_k2[ROWS];
__device__ float g_ctx[ROWS*HDIM];
__device__ float g_outs[ROWS*HDIM];

// ================= cp.async helpers =================
__device__ __forceinline__ void cpa16(void* dst_smem, const void* src) {
    unsigned d = (unsigned)__cvta_generic_to_shared(dst_smem);
    asm volatile("cp.async.cg.shared.global [%0], [%1], 16;\n" :: "r"(d), "l"(src));
}
#define CP_COMMIT() asm volatile("cp.async.commit_group;\n")
#define CP_WAIT(N)  asm volatile("cp.async.wait_group %0;\n" :: "n"(N))

// ================= mma wrappers =================
__device__ __forceinline__ float tf32_rna(float x) {
    uint32_t r; asm("cvt.rna.tf32.f32 %0, %1;\n" : "=r"(r) : "f"(x));
    return __uint_as_float(r);
}
__device__ __forceinline__ void mma_tf32(float& d0, float& d1, float& d2, float& d3,
                                         float a0, float a1, float a2, float a3,
                                         float b0, float b1)
{
    asm volatile(
        "mma.sync.aligned.m16n8k8.row.col.f32.tf32.tf32.f32 "
        "{%0,%1,%2,%3}, {%4,%5,%6,%7}, {%8,%9}, {%0,%1,%2,%3};\n"
        : "+f"(d0), "+f"(d1), "+f"(d2), "+f"(d3)
        : "r"(__float_as_uint(a0)), "r"(__float_as_uint(a1)),
          "r"(__float_as_uint(a2)), "r"(__float_as_uint(a3)),
          "r"(__float_as_uint(b0)), "r"(__float_as_uint(b1)));
}
__device__ __forceinline__ void mma3_tf32(float* acc,
    float ab0, float ab1, float ab2, float ab3,
    float as0, float as1, float as2, float as3,
    float b0, float b1)
{
    float bb0 = tf32_rna(b0), bb1 = tf32_rna(b1);
    float bs0 = b0 - bb0,     bs1 = b1 - bb1;
    mma_tf32(acc[0], acc[1], acc[2], acc[3], ab0, ab1, ab2, ab3, bb0, bb1);
    mma_tf32(acc[0], acc[1], acc[2], acc[3], ab0, ab1, ab2, ab3, bs0, bs1);
    mma_tf32(acc[0], acc[1], acc[2], acc[3], as0, as1, as2, as3, bb0, bb1);
}
__device__ __forceinline__ void mma_bf16(float* acc,
    uint32_t a0, uint32_t a1, uint32_t a2, uint32_t a3, uint32_t b0, uint32_t b1)
{
    asm volatile(
        "mma.sync.aligned.m16n8k16.row.col.f32.bf16.bf16.f32 "
        "{%0,%1,%2,%3}, {%4,%5,%6,%7}, {%8,%9}, {%0,%1,%2,%3};\n"
        : "+f"(acc[0]), "+f"(acc[1]), "+f"(acc[2]), "+f"(acc[3])
        : "r"(a0), "r"(a1), "r"(a2), "r"(a3), "r"(b0), "r"(b1));
}
__device__ __forceinline__ uint32_t pack_bf(float x0, float x1) {
    uint32_t r; asm("cvt.rn.bf16x2.f32 %0, %1, %2;\n" : "=r"(r) : "f"(x1), "f"(x0));
    return r;
}
__device__ __forceinline__ void split_bf(float x0, float x1, uint32_t& hi, uint32_t& lo) {
    hi = pack_bf(x0, x1);
    float h0 = __uint_as_float(hi << 16);
    float h1 = __uint_as_float(hi & 0xffff0000u);
    lo = pack_bf(x0 - h0, x1 - h1);
}

// ---- dummy kernels to shift the ncu -s window onto k_attn2 ----
__global__ void k_nop1() {}
__global__ void k_nop2() {}

// ================= projections via tensor cores (3xTF32) =================
#define PJ_WS (64*132)
#define PJ_SQ (PJ_WS + 128*72)
#define PJ_BYTES ((PJ_SQ + 128) * 4)

__global__ __launch_bounds__(256) void k_proj(
    const float* __restrict__ qs, const float* __restrict__ ks, const float* __restrict__ vs,
    const float* __restrict__ Wq, const float* __restrict__ bq,
    const float* __restrict__ Wk, const float* __restrict__ bk,
    const float* __restrict__ Wv, const float* __restrict__ bv)
{
    extern __shared__ float psm[];
    float* Xs  = psm;
    float* Ws  = psm + PJ_WS;
    float* sqp = psm + PJ_SQ;

    const float* X; const float* W; const float* bias; float* Y; float* sq;
    int mode = blockIdx.y;
    switch (mode) {
        case 0:  X = qs; W = Wq; bias = bq; Y = g_q; sq = g_q2; break;
        case 1:  X = ks; W = Wk; bias = bk; Y = g_k; sq = g_k2; break;
        default: X = vs; W = Wv; bias = bv; Y = nullptr; sq = nullptr; break;
    }
    const int tid  = threadIdx.x;
    const int lane = tid & 31;
    const int wid  = tid >> 5;
    const int g    = lane >> 2;
    const int tig  = lane & 3;
    const int wm   = wid & 3;
    const int wn   = wid >> 2;
    const int row0 = blockIdx.x * 64;

    #pragma unroll
    for (int it = 0; it < 8; it++) {
        int op = it * 256 + tid;
        int r = op >> 5, c = (op & 31) * 4;
        cpa16(&Xs[r * 132 + c], &X[(size_t)(row0 + r) * DIN + c]);
    }
    #pragma unroll
    for (int it = 0; it < 8; it++) {
        int op = it * 256 + tid;
        int r = op >> 4, c = (op & 15) * 4;
        cpa16(&Ws[r * 72 + c], &W[(size_t)r * HDIM + c]);
    }
    CP_COMMIT(); CP_WAIT(0);
    __syncthreads();

    float acc[4][4];
    #pragma unroll
    for (int i = 0; i < 4; i++)
        #pragma unroll
        for (int j = 0; j < 4; j++) acc[i][j] = 0.f;

    #pragma unroll
    for (int kk = 0; kk < 16; kk++) {
        int ar = (wm * 16 + g) * 132 + kk * 8 + tig;
        float a0 = Xs[ar], a1 = Xs[ar + 8 * 132], a2 = Xs[ar + 4], a3 = Xs[ar + 8 * 132 + 4];
        float ab0 = tf32_rna(a0), ab1 = tf32_rna(a1), ab2 = tf32_rna(a2), ab3 = tf32_rna(a3);
        float as0 = a0 - ab0, as1 = a1 - ab1, as2 = a2 - ab2, as3 = a3 - ab3;
        #pragma unroll
        for (int nt = 0; nt < 4; nt++) {
            int br = (kk * 8 + tig) * 72 + wn * 32 + nt * 8 + g;
            float b0 = Ws[br], b1 = Ws[br + 4 * 72];
            mma3_tf32(acc[nt], ab0, ab1, ab2, ab3, as0, as1, as2, as3, b0, b1);
        }
    }

    const int rr = row0 + wm * 16 + g;
    float p0 = 0.f, p1 = 0.f;
    if (mode == 2) {
        int bb_ = rr >> 11;
        int s   = rr & (SEQ - 1);
        #pragma unroll
        for (int nt = 0; nt < 4; nt++) {
            int c = wn * 32 + nt * 8 + 2 * tig;
            float2 bbv = *(const float2*)&bias[c];
            float y[4] = { acc[nt][0] + bbv.x, acc[nt][1] + bbv.y,
                           acc[nt][2] + bbv.x, acc[nt][3] + bbv.y };
            size_t base0 = ((size_t)bb_ * HDIM + c) * SEQ;
            size_t base1 = base0 + SEQ;
            size_t idx[4] = { base0 + s, base1 + s, base0 + s + 8, base1 + s + 8 };
            #pragma unroll
            for (int j = 0; j < 4; j++) {
                __nv_bfloat16 h = __float2bfloat16_rn(y[j]);
                float hf = __uint_as_float(((uint32_t)__bfloat16_as_ushort(h)) << 16);
                g_vth[idx[j]] = h;
                g_vtl[idx[j]] = __float2bfloat16_rn(y[j] - hf);
            }
        }
    } else {
        #pragma unroll
        for (int nt = 0; nt < 4; nt++) {
            int c = wn * 32 + nt * 8 + 2 * tig;
            float2 bbv = *(const float2*)&bias[c];
            float y00 = acc[nt][0] + bbv.x, y01 = acc[nt][1] + bbv.y;
            float y10 = acc[nt][2] + bbv.x, y11 = acc[nt][3] + bbv.y;
            p0 += y00 * y00 + y01 * y01;
            p1 += y10 * y10 + y11 * y11;
            *(float2*)&Y[(size_t)rr * HDIM + c]       = make_float2(y00, y01);
            *(float2*)&Y[(size_t)(rr + 8) * HDIM + c] = make_float2(y10, y11);
        }
        p0 += __shfl_xor_sync(0xffffffffu, p0, 1);
        p0 += __shfl_xor_sync(0xffffffffu, p0, 2);
        p1 += __shfl_xor_sync(0xffffffffu, p1, 1);
        p1 += __shfl_xor_sync(0xffffffffu, p1, 2);
        if (tig == 0) {
            sqp[wn * 64 + wm * 16 + g]     = p0;
            sqp[wn * 64 + wm * 16 + g + 8] = p1;
        }
        __syncthreads();
        if (tid < 64) sq[row0 + tid] = sqp[tid] + sqp[64 + tid];
    }
}

// ======== fused attention: 256 threads, 8 warps (2m x 4n), TQ=32, KT=64, 2 CTAs/SM ========
// byte offsets
#define OFF_QS   0                         // f32 [32][68]  = 8704 B
#define OFF_KS0  8704                      // f32 [64][76]  = 19456 B
#define OFF_KS1  (OFF_KS0 + 19456)
#define OFF_VH0  (OFF_KS1 + 19456)         // bf16 [64][72] = 9216 B
#define OFF_VH1  (OFF_VH0 + 9216)
#define OFF_VL0  (OFF_VH1 + 9216)
#define OFF_VL1  (OFF_VL0 + 9216)
#define OFF_K20  (OFF_VL1 + 9216)          // f32 [64] = 256 B
#define OFF_K21  (OFF_K20 + 256)
#define OFF_RED  (OFF_K21 + 256)           // f32 [4][32] = 512 B
#define OFF_RINV (OFF_RED + 512)           // f32 [32]
#define SMEM_BYTES (OFF_RINV + 128)        // 85760
#define OFF_CT   OFF_KS0                   // ctmp f32 [4][32][68] = 34816 B (fits in KS0+KS1)

__global__ __launch_bounds__(256, 2) void k_attn2(float* __restrict__ attn, int do_attn)
{
    extern __shared__ char smc[];
    float* Qs = (float*)(smc + OFF_QS);
    float* KsB[2] = { (float*)(smc + OFF_KS0), (float*)(smc + OFF_KS1) };
    __nv_bfloat16* VhB[2] = { (__nv_bfloat16*)(smc + OFF_VH0), (__nv_bfloat16*)(smc + OFF_VH1) };
    __nv_bfloat16* VlB[2] = { (__nv_bfloat16*)(smc + OFF_VL0), (__nv_bfloat16*)(smc + OFF_VL1) };
    float* k2B[2] = { (float*)(smc + OFF_K20), (float*)(smc + OFF_K21) };
    float* red  = (float*)(smc + OFF_RED);
    float* rinv = (float*)(smc + OFF_RINV);
    float* ctmp = (float*)(smc + OFF_CT);

    const int tid  = threadIdx.x;
    const int lane = tid & 31;
    const int wid  = tid >> 5;       // 0..7
    const int g    = lane >> 2;
    const int tig  = lane & 3;
    const int wm   = wid & 1;        // 2 m-tiles of 16 rows
    const int wn   = wid >> 1;       // 4 n/k quarters (16 cols each)

    const int row0 = blockIdx.x * TQ;
    const int b    = row0 >> 11;
    const float* k_base  = g_k + (size_t)b * SEQ * HDIM;
    const __nv_bfloat16* vh_base = g_vth + (size_t)b * HDIM * SEQ;
    const __nv_bfloat16* vl_base = g_vtl + (size_t)b * HDIM * SEQ;
    const float* k2_base = g_k2 + b * SEQ;

    // ---- prologue staging ----
    #pragma unroll
    for (int it = 0; it < 2; it++) {                  // Q: 32 rows x 16 float4 = 512 ops
        int op = it * 256 + tid;
        int r = op >> 4, c = (op & 15) * 4;
        cpa16(&Qs[r * 68 + c], &g_q[(size_t)(row0 + r) * HDIM + c]);
    }
    #pragma unroll
    for (int it = 0; it < 4; it++) {                  // K: 64 rows x 16 float4 = 1024 ops
        int op = it * 256 + tid;
        int r = op >> 4, c = (op & 15) * 4;
        cpa16(&KsB[0][r * 76 + c], k_base + (size_t)r * HDIM + c);
    }
    #pragma unroll
    for (int it = 0; it < 2; it++) {                  // Vh,Vl: 64 h x 8 chunks = 512 ops each
        int op = it * 256 + tid;
        int h = op >> 3, ch = (op & 7) * 8;
        cpa16(&VhB[0][h * 72 + ch], vh_base + (size_t)h * SEQ + ch);
        cpa16(&VlB[0][h * 72 + ch], vl_base + (size_t)h * SEQ + ch);
    }
    if (tid < 16) cpa16(&k2B[0][tid * 4], k2_base + tid * 4);
    CP_COMMIT();

    float q2r0 = g_q2[row0 + wm * 16 + g];
    float q2r1 = g_q2[row0 + wm * 16 + g + 8];

    float rs0 = 0.f, rs1 = 0.f;
    float cacc[8][4];
    #pragma unroll
    for (int i = 0; i < 8; i++)
        #pragma unroll
        for (int j = 0; j < 4; j++) cacc[i][j] = 0.f;

    for (int kb = 0; kb < NKB2; kb++) {
        const int bf = kb & 1;
        if (kb + 1 < NKB2) {
            const int nb = (kb + 1) & 1;
            const float* kn = k_base + (size_t)(kb + 1) * KT2 * HDIM;
            const __nv_bfloat16* vhn = vh_base + (kb + 1) * KT2;
            const __nv_bfloat16* vln = vl_base + (kb + 1) * KT2;
            #pragma unroll
            for (int it = 0; it < 4; it++) {
                int op = it * 256 + tid;
                int r = op >> 4, c = (op & 15) * 4;
                cpa16(&KsB[nb][r * 76 + c], kn + (size_t)r * HDIM + c);
            }
            #pragma unroll
            for (int it = 0; it < 2; it++) {
                int op = it * 256 + tid;
                int h = op >> 3, ch = (op & 7) * 8;
                cpa16(&VhB[nb][h * 72 + ch], vhn + (size_t)h * SEQ + ch);
                cpa16(&VlB[nb][h * 72 + ch], vln + (size_t)h * SEQ + ch);
            }
            if (tid < 16) cpa16(&k2B[nb][tid * 4], k2_base + (kb + 1) * KT2 + tid * 4);
            CP_COMMIT();
            CP_WAIT(1);
        } else {
            CP_WAIT(0);
        }
        __syncthreads();

        const float* Ks  = KsB[bf];
        const __nv_bfloat16* Vh = VhB[bf];
        const __nv_bfloat16* Vl = VlB[bf];
        const float* k2s = k2B[bf];

        // ---- scores (1x tf32): warp tile 16 x 16 (cols wn*16..+16) ----
        float e[2][4];
        #pragma unroll
        for (int nt = 0; nt < 2; nt++) {
            e[nt][0] = 0.f; e[nt][1] = 0.f; e[nt][2] = 0.f; e[nt][3] = 0.f;
        }
        #pragma unroll
        for (int kk = 0; kk < 8; kk++) {
            int ar = (wm * 16 + g) * 68 + kk * 8 + tig;
            float a0 = Qs[ar];
            float a1 = Qs[ar + 8 * 68];
            float a2 = Qs[ar + 4];
            float a3 = Qs[ar + 8 * 68 + 4];
            #pragma unroll
            for (int nt = 0; nt < 2; nt++) {
                int br = (wn * 16 + nt * 8 + g) * 76 + kk * 8 + tig;
                float b0 = Ks[br], b1 = Ks[br + 4];
                mma_tf32(e[nt][0], e[nt][1], e[nt][2], e[nt][3], a0, a1, a2, a3, b0, b1);
            }
        }

        // ---- exp in place + rowsum partial + attn store ----
        #pragma unroll
        for (int nt = 0; nt < 2; nt++) {
            int cg = wn * 16 + nt * 8 + 2 * tig;
            float2 k2p = *(const float2*)&k2s[cg];
            float e00 = __expf(-0.125f * (q2r0 + k2p.x - 2.f * e[nt][0]));
            float e01 = __expf(-0.125f * (q2r0 + k2p.y - 2.f * e[nt][1]));
            float e10 = __expf(-0.125f * (q2r1 + k2p.x - 2.f * e[nt][2]));
            float e11 = __expf(-0.125f * (q2r1 + k2p.y - 2.f * e[nt][3]));
            e[nt][0] = e00; e[nt][1] = e01; e[nt][2] = e10; e[nt][3] = e11;
            rs0 += e00 + e01;
            rs1 += e10 + e11;
            if (do_attn) {
                size_t a0i = (size_t)(row0 + wm * 16 + g) * SEQ + kb * KT2 + cg;
                *(float2*)&attn[a0i]           = make_float2(e00, e01);
                *(float2*)&attn[a0i + 8 * SEQ] = make_float2(e10, e11);
            }
        }

        // ---- ctx (3x bf16 m16n8k16): warp consumes its own 16 k-cols ----
        {
            uint32_t ah0, ah1, ah2, ah3, al0, al1, al2, al3;
            split_bf(e[0][0], e[0][1], ah0, al0);   // row g,   k 2tig..+1
            split_bf(e[0][2], e[0][3], ah1, al1);   // row g+8
            split_bf(e[1][0], e[1][1], ah2, al2);   // row g,   k 2tig+8..+9
            split_bf(e[1][2], e[1][3], ah3, al3);   // row g+8
            int sb = wn * 16 + 2 * tig;             // k index within 64-tile
            #pragma unroll
            for (int nt = 0; nt < 8; nt++) {
                int vr = (nt * 8 + g) * 72 + sb;
                uint32_t bh0 = *(const uint32_t*)&Vh[vr];
                uint32_t bh1 = *(const uint32_t*)&Vh[vr + 8];
                uint32_t bl0 = *(const uint32_t*)&Vl[vr];
                uint32_t bl1 = *(const uint32_t*)&Vl[vr + 8];
                mma_bf16(cacc[nt], ah0, ah1, ah2, ah3, bh0, bh1);
                mma_bf16(cacc[nt], al0, al1, al2, al3, bh0, bh1);
                mma_bf16(cacc[nt], ah0, ah1, ah2, ah3, bl0, bl1);
            }
        }
        __syncthreads();
    }

    // ---- rowsum reduce (4 wn quarters per row) -> rinv ----
    rs0 += __shfl_xor_sync(0xffffffffu, rs0, 1);
    rs0 += __shfl_xor_sync(0xffffffffu, rs0, 2);
    rs1 += __shfl_xor_sync(0xffffffffu, rs1, 1);
    rs1 += __shfl_xor_sync(0xffffffffu, rs1, 2);
    if (tig == 0) {
        red[wn * 32 + wm * 16 + g]     = rs0;
        red[wn * 32 + wm * 16 + g + 8] = rs1;
    }
    __syncthreads();
    if (tid < 32)
        rinv[tid] = 1.0f / (red[tid] + red[32 + tid] + red[64 + tid] + red[96 + tid]);
    __syncthreads();   // all K/V reads complete before ctmp aliasing

    // ---- combine ctx quarters via ctmp (aliased over dead K smem) ----
    #pragma unroll
    for (int nt = 0; nt < 8; nt++) {
        int c = nt * 8 + 2 * tig;
        *(float2*)&ctmp[wn * 32 * 68 + (wm * 16 + g) * 68 + c]     = make_float2(cacc[nt][0], cacc[nt][1]);
        *(float2*)&ctmp[wn * 32 * 68 + (wm * 16 + g + 8) * 68 + c] = make_float2(cacc[nt][2], cacc[nt][3]);
    }
    __syncthreads();
    #pragma unroll
    for (int it = 0; it < 8; it++) {
        int idx = it * 256 + tid;         // 0..2047
        int r = idx >> 6, c = idx & 63;
        float s = ctmp[r * 68 + c] + ctmp[32 * 68 + r * 68 + c]
                + ctmp[2 * 32 * 68 + r * 68 + c] + ctmp[3 * 32 * 68 + r * 68 + c];
        g_ctx[(size_t)(row0 + r) * HDIM + c] = s * rinv[r];
    }

    // ---- normalize attn in place ----
    if (do_attn) {
        for (int kb = 0; kb < NKB2; kb++) {
            #pragma unroll
            for (int it = 0; it < 2; it++) {
                int f = it * 256 + tid;           // 512 float4 = 32 rows x 16 float4
                int r = f >> 4, c4 = (f & 15) * 4;
                float ri = rinv[r];
                float* p = &attn[(size_t)(row0 + r) * SEQ + kb * KT2 + c4];
                float4 v4 = *(float4*)p;
                v4.x *= ri; v4.y *= ri; v4.z *= ri; v4.w *= ri;
                *(float4*)p = v4;
            }
        }
    }
}

// ============== out = ctx @ Wo + bo ==============
__global__ __launch_bounds__(256) void k_out(
    const float* __restrict__ Wo, const float* __restrict__ bo, float* __restrict__ out)
{
    __shared__ float cs[4][64];
    int tid = threadIdx.x;
    int r = tid >> 6, h = tid & 63;
    int row = blockIdx.x * 4 + r;
    cs[r][h] = g_ctx[(size_t)row * HDIM + h];
    __syncthreads();
    float o = bo[h];
    #pragma unroll 16
    for (int hp = 0; hp < HDIM; hp++) o += cs[r][hp] * Wo[hp * HDIM + h];
    out[(size_t)row * HDIM + h] = o;
}

// =========================== launch ===========================
extern "C" void kernel_launch(void* const* d_in, const int* in_sizes, int n_in,
                              void* d_out, int out_size)
{
    const float* qs = (const float*)d_in[0];
    const float* ks = (const float*)d_in[1];
    const float* vs = (const float*)d_in[2];
    const float* Wq = (const float*)d_in[3];
    const float* bq = (const float*)d_in[4];
    const float* Wk = (const float*)d_in[5];
    const float* bk = (const float*)d_in[6];
    const float* Wv = (const float*)d_in[7];
    const float* bv = (const float*)d_in[8];
    const float* Wo = (const float*)d_in[9];
    const float* bo = (const float*)d_in[10];

    const int OUTN = ROWS * HDIM;        // 524288
    const int ATTN = ROWS * SEQ;         // 16777216

    float* souts = nullptr;
    cudaGetSymbolAddress((void**)&souts, g_outs);

    float* outp; float* attnp;
    if (out_size >= OUTN + ATTN)      { outp = (float*)d_out; attnp = (float*)d_out + OUTN; }
    else if (out_size == ATTN)        { outp = souts;         attnp = (float*)d_out; }
    else                              { outp = (float*)d_out; attnp = nullptr; }

    cudaFuncSetAttribute(k_proj,  cudaFuncAttributeMaxDynamicSharedMemorySize, PJ_BYTES);
    cudaFuncSetAttribute(k_attn2, cudaFuncAttributeMaxDynamicSharedMemorySize, SMEM_BYTES);

    k_nop1<<<1, 32>>>();
    k_nop2<<<1, 32>>>();
    k_proj<<<dim3(ROWS / 64, 3), 256, PJ_BYTES>>>(qs, ks, vs, Wq, bq, Wk, bk, Wv, bv);
    k_attn2<<<ROWS / TQ, 256, SMEM_BYTES>>>(attnp ? attnp : (float*)d_out,
                                            attnp != nullptr ? 1 : 0);
    k_out<<<ROWS / 4, 256>>>(Wo, bo, outp);
}